// round 10
// baseline (speedup 1.0000x reference)
#include <cuda_runtime.h>

typedef unsigned long long ull;

#define TT 1024
#define BB 32
#define DD 768
#define LLn 48
#define SSTRIDE (BB * LLn)   // 1536 floats per time step

// Scratch (static device globals — no allocation)
__device__ float g_eem[TT * BB * LLn];   // exp(em + bias), layout [t][b][l]
__device__ float g_eemM[TT * BB * LLn];  // tags ? 0 : eem  (for partial chain)
__device__ int   g_bool_dt;              // 0=uint8, 1=int32, 2=float32

__device__ __forceinline__ ull pack2(float x, float y) {
    ull r; asm("mov.b64 %0, {%1,%2};" : "=l"(r) : "f"(x), "f"(y)); return r;
}
__device__ __forceinline__ void unpack2(ull v, float& x, float& y) {
    asm("mov.b64 {%0,%1}, %2;" : "=f"(x), "=f"(y) : "l"(v));
}
__device__ __forceinline__ ull fma2(ull a, ull b, ull c) {
    ull d; asm("fma.rn.f32x2 %0, %1, %2, %3;" : "=l"(d) : "l"(a), "l"(b), "l"(c)); return d;
}
__device__ __forceinline__ ull add2(ull a, ull b) {
    ull d; asm("add.rn.f32x2 %0, %1, %2;" : "=l"(d) : "l"(a), "l"(b)); return d;
}

__device__ __forceinline__ int loadBool(const void* p, int dt, long idx) {
    if (dt == 1) return ((const int*)p)[idx] != 0;
    if (dt == 0) return ((const unsigned char*)p)[idx] != 0;
    return ((const float*)p)[idx] != 0.f;
}

// ---------------------------------------------------------------------------
// Detect boolean storage dtype from the tags buffer (~30% true rate).
// ---------------------------------------------------------------------------
__global__ void detect_kernel(const unsigned int* __restrict__ w) {
    int i = threadIdx.x;
    int f = 0, u = 0;
#pragma unroll
    for (int q = 0; q < 4; q++) {
        unsigned int v = w[i + q * 256];
        if (v == 0x3F800000u) f = 1;
        else if (v & 0xFFFFFF00u) u = 1;
    }
    int anyf = __syncthreads_or(f);
    int anyu = __syncthreads_or(u);
    if (i == 0) g_bool_dt = anyf ? 2 : (anyu ? 0 : 1);
}

// ---------------------------------------------------------------------------
// Emissions GEMM + exp: eem[t][b][j] = exp(feats[t,b,:].W[:,j] + bias[j])
// CTA = 256 threads = 128 rows x 2 column-halves (12 ull acc each).
// ---------------------------------------------------------------------------
#define KT 32
__global__ __launch_bounds__(256) void emis_kernel(const float* __restrict__ feats,
                                                   const float* __restrict__ W,
                                                   const float* __restrict__ bias) {
    __shared__ float2 As[128 * 17];   // 128 rows x (16 f2 + pad) = 17 KB
    __shared__ float  Ws[KT * LLn];   // 32 x 48 = 6 KB
    const int tid = threadIdx.x;
    const int r = tid >> 1;           // row within CTA
    const int h = tid & 1;            // column half (0: j<24, 1: j>=24)
    const int base_row = blockIdx.x * 128;

    ull acc[12];
#pragma unroll
    for (int i = 0; i < 12; i++) acc[i] = 0ull;

    for (int kt = 0; kt < DD / KT; ++kt) {
        __syncthreads();
        {
            const float2* fg = (const float2*)(feats);
#pragma unroll
            for (int q = 0; q < 8; q++) {
                int n = q * 256 + tid;
                int rr = n >> 4;
                int c2 = n & 15;
                As[rr * 17 + c2] = fg[(size_t)(base_row + rr) * (DD / 2) + kt * (KT / 2) + c2];
            }
        }
        {
            const float4* wg = (const float4*)(W + kt * KT * LLn);
            float4* ws4 = (float4*)Ws;
            for (int n = tid; n < KT * LLn / 4; n += 256) ws4[n] = wg[n];
        }
        __syncthreads();

        const float2* arow = As + r * 17;
#pragma unroll
        for (int k2 = 0; k2 < 16; k2++) {
            float2 a2 = arow[k2];
            ull d0 = pack2(a2.x, a2.x);
            ull d1 = pack2(a2.y, a2.y);
            const ulonglong2* w0 = (const ulonglong2*)(Ws + (2 * k2) * LLn + h * 24);
            const ulonglong2* w1 = (const ulonglong2*)(Ws + (2 * k2 + 1) * LLn + h * 24);
#pragma unroll
            for (int j = 0; j < 6; j++) {
                ulonglong2 wa = w0[j];
                ulonglong2 wb = w1[j];
                acc[2 * j]     = fma2(d0, wa.x, acc[2 * j]);
                acc[2 * j + 1] = fma2(d0, wa.y, acc[2 * j + 1]);
                acc[2 * j]     = fma2(d1, wb.x, acc[2 * j]);
                acc[2 * j + 1] = fma2(d1, wb.y, acc[2 * j + 1]);
            }
        }
    }
    const int grow = base_row + r;       // = t*32 + b
    float* orow = g_eem + (size_t)grow * LLn + h * 24;
#pragma unroll
    for (int jp = 0; jp < 12; jp++) {
        float x, y; unpack2(acc[jp], x, y);
        float2 o;
        o.x = __expf(x + bias[h * 24 + 2 * jp]);
        o.y = __expf(y + bias[h * 24 + 2 * jp + 1]);
        ((float2*)orow)[jp] = o;
    }
}

// ---------------------------------------------------------------------------
// eemM = tags ? 0 : eem  (fully coalesced, float4/int4 vectorized)
// ---------------------------------------------------------------------------
__global__ __launch_bounds__(256) void mask_kernel(const void* __restrict__ tags) {
    int i = blockIdx.x * 256 + threadIdx.x;   // float4 index
    float4 e = ((const float4*)g_eem)[i];
    int dt = g_bool_dt;
    int b0, b1, b2, b3;
    if (dt == 1) {
        int4 t = ((const int4*)tags)[i];
        b0 = t.x != 0; b1 = t.y != 0; b2 = t.z != 0; b3 = t.w != 0;
    } else if (dt == 0) {
        uchar4 t = ((const uchar4*)tags)[i];
        b0 = t.x != 0; b1 = t.y != 0; b2 = t.z != 0; b3 = t.w != 0;
    } else {
        float4 t = ((const float4*)tags)[i];
        b0 = t.x != 0.f; b1 = t.y != 0.f; b2 = t.z != 0.f; b3 = t.w != 0.f;
    }
    if (b0) e.x = 0.f;
    if (b1) e.y = 0.f;
    if (b2) e.z = 0.f;
    if (b3) e.w = 0.f;
    ((float4*)g_eemM)[i] = e;
}

// ---------------------------------------------------------------------------
// CRF forward scan: ONE WARP per chain, state entirely in registers.
// CTA per batch (64 threads): warp0 = fwd, warp1 = par — independent until a
// single final __syncthreads. Lane l owns rows l and 32+l (B-row zero for
// lanes >= 16 via E=0). Per step: 48 shfl broadcasts + 48 packed fma2,
// NO smem, NO barriers. Renorm every 8 steps at a static unroll slot.
// ---------------------------------------------------------------------------
__global__ __launch_bounds__(64) void scan_kernel(float* __restrict__ out,
                                                  const int* __restrict__ lens,
                                                  const float* __restrict__ beg,
                                                  const float* __restrict__ trans,
                                                  const float* __restrict__ endv,
                                                  const void* __restrict__ bc,
                                                  const void* __restrict__ ec,
                                                  const void* __restrict__ tc) {
    __shared__ float res2[2];
    const int tid = threadIdx.x;
    const int w = tid >> 5;              // 0 = fwd, 1 = par
    const int l = tid & 31;
    const bool is_par = (w == 1);
    const bool hasB = l < 16;
    const int rB = hasB ? 32 + l : 0;    // clamped for safe loads
    const int b = blockIdx.x;
    const int lenm1 = lens[b] - 1;
    const int dt = g_bool_dt;
    const float* gbA = (is_par ? g_eemM : g_eem) + b * LLn + l;
    const float* gbB = (is_par ? g_eemM : g_eem) + b * LLn + rB;

    // E2[k] = (exp(trans[l][k]), exp(trans[32+l][k])), constraint-masked.
    ull E2[LLn];
#pragma unroll
    for (int k = 0; k < LLn; k++) {
        float eA = __expf(trans[l * LLn + k]);
        if (is_par && loadBool(tc, dt, l * LLn + k)) eA = 0.f;
        float eB = 0.f;
        if (hasB) {
            eB = __expf(trans[rB * LLn + k]);
            if (is_par && loadBool(tc, dt, rB * LLn + k)) eB = 0.f;
        }
        E2[k] = pack2(eA, eB);
    }
    float EendA = __expf(endv[l]);
    if (is_par && loadBool(ec, dt, l)) EendA = 0.f;
    float EendB = 0.f;
    if (hasB) {
        EendB = __expf(endv[rB]);
        if (is_par && loadBool(ec, dt, rB)) EendB = 0.f;
    }

    // t = 0 init (eemM folds tags; bc applied here). State in registers.
    float uA, uB;
    {
        uA = __ldg(gbA) * __expf(beg[l]);
        if (is_par && loadBool(bc, dt, l)) uA = 0.f;
        uB = 0.f;
        if (hasB) {
            uB = __ldg(gbB) * __expf(beg[rB]);
            if (is_par && loadBool(bc, dt, rB)) uB = 0.f;
        }
    }

    float c = 0.f;
    int t = 1;

    auto ldA = [&](int tt) -> float {
        int tq = (tt <= TT - 1) ? tt : (TT - 1);
        return __ldg(gbA + (size_t)tq * SSTRIDE);
    };
    auto ldB = [&](int tt) -> float {
        int tq = (tt <= TT - 1) ? tt : (TT - 1);
        return __ldg(gbB + (size_t)tq * SSTRIDE);
    };

    // One recurrence step: u_new[j] = (sum_k E[j][k] u[k]) * em[j]
    // 48 shuffle broadcasts of u, each feeding one packed fma2 (rows l, 32+l).
    auto step = [&](float peA, float peB) {
        ull a0 = 0, a1 = 0, a2 = 0, a3 = 0;
#pragma unroll
        for (int k = 0; k < 32; k += 4) {
            float b0 = __shfl_sync(0xffffffffu, uA, k);
            float b1 = __shfl_sync(0xffffffffu, uA, k + 1);
            float b2 = __shfl_sync(0xffffffffu, uA, k + 2);
            float b3 = __shfl_sync(0xffffffffu, uA, k + 3);
            a0 = fma2(E2[k],     pack2(b0, b0), a0);
            a1 = fma2(E2[k + 1], pack2(b1, b1), a1);
            a2 = fma2(E2[k + 2], pack2(b2, b2), a2);
            a3 = fma2(E2[k + 3], pack2(b3, b3), a3);
        }
#pragma unroll
        for (int k = 0; k < 16; k += 4) {
            float b0 = __shfl_sync(0xffffffffu, uB, k);
            float b1 = __shfl_sync(0xffffffffu, uB, k + 1);
            float b2 = __shfl_sync(0xffffffffu, uB, k + 2);
            float b3 = __shfl_sync(0xffffffffu, uB, k + 3);
            a0 = fma2(E2[32 + k],     pack2(b0, b0), a0);
            a1 = fma2(E2[32 + k + 1], pack2(b1, b1), a1);
            a2 = fma2(E2[32 + k + 2], pack2(b2, b2), a2);
            a3 = fma2(E2[32 + k + 3], pack2(b3, b3), a3);
        }
        a0 = add2(a0, a2); a1 = add2(a1, a3); a0 = add2(a0, a1);
        float dA, dB; unpack2(a0, dA, dB);
        uA = dA * peA;
        uB = dB * peB;   // E B-row == 0 on lanes >= 16  ->  uB stays 0
    };

    // rotating 8-slot emission prefetch (static indices -> stays in regs)
    float eA[8], eB[8];
#pragma unroll
    for (int i = 0; i < 8; i++) { eA[i] = ldA(1 + i); eB[i] = ldB(1 + i); }

    // ---- main loop: groups of 8 branch-free steps, renorm at slot 7 ----
    while (t + 8 <= lenm1) {
#pragma unroll
        for (int i = 0; i < 8; i++) {
            float pA = eA[i], pB = eB[i];
            eA[i] = ldA(t + 8 + i);
            eB[i] = ldB(t + 8 + i);
            step(pA, pB);
            if (i == 7) {                    // compile-time slot: branch-free
                float m = fmaxf(uA, uB);
#pragma unroll
                for (int off = 16; off >= 1; off >>= 1)
                    m = fmaxf(m, __shfl_xor_sync(0xffffffffu, m, off));
                m = fmaxf(m, 1e-30f);
                float inv = __fdividef(1.f, m);
                uA *= inv; uB *= inv;
                c += __logf(m);
            }
        }
        t += 8;
    }

    // ---- tail: r plain steps (r in [0,7]), then the final step ----
    const int r = lenm1 - t;
    float fA = eA[0], fB = eB[0];
#pragma unroll
    for (int i = 0; i < 8; i++) if (i == r) { fA = eA[i]; fB = eB[i]; }

#pragma unroll
    for (int i = 0; i < 7; i++) {
        if (i < r) step(eA[i], eB[i]);
    }

    // final step (t == lenm1): emission + end transition + logsumexp readout
    {
        step(fA, fB);
        float s = uA * EendA + uB * EendB;   // EendB==0 on dummy lanes
#pragma unroll
        for (int off = 16; off >= 1; off >>= 1)
            s += __shfl_xor_sync(0xffffffffu, s, off);
        if (l == 0) res2[w] = c + __logf(s);
    }

    __syncthreads();
    if (tid == 0) out[b] = res2[0] - res2[1];
}

extern "C" void kernel_launch(void* const* d_in, const int* in_sizes, int n_in,
                              void* d_out, int out_size) {
    const float* feats = (const float*)d_in[0];
    const void*  tags  = d_in[1];
    const int*   lens  = (const int*)d_in[2];
    const float* W     = (const float*)d_in[3];
    const float* bias  = (const float*)d_in[4];
    const float* beg   = (const float*)d_in[5];
    const float* trans = (const float*)d_in[6];
    const float* endv  = (const float*)d_in[7];
    const void*  bc    = d_in[8];
    const void*  ec    = d_in[9];
    const void*  tc    = d_in[10];

    emis_kernel<<<256, 256>>>(feats, W, bias);
    detect_kernel<<<1, 256>>>((const unsigned int*)tags);
    mask_kernel<<<TT * BB * LLn / 4 / 256, 256>>>(tags);
    scan_kernel<<<BB, 64>>>((float*)d_out, lens, beg, trans, endv, bc, ec, tc);
}

// round 12
// speedup vs baseline: 1.1025x; 1.1025x over previous
#include <cuda_runtime.h>

typedef unsigned long long ull;

#define TT 1024
#define BB 32
#define DD 768
#define LLn 48
#define SSTRIDE (BB * LLn)   // 1536 floats per time step

// Scratch (static device globals — no allocation)
__device__ float g_eem[TT * BB * LLn];   // exp(em + bias), layout [t][b][l]
__device__ float g_eemM[TT * BB * LLn];  // tags ? 0 : eem  (for partial chain)
__device__ int   g_bool_dt;              // 0=uint8, 1=int32, 2=float32

__device__ __forceinline__ ull pack2(float x, float y) {
    ull r; asm("mov.b64 %0, {%1,%2};" : "=l"(r) : "f"(x), "f"(y)); return r;
}
__device__ __forceinline__ void unpack2(ull v, float& x, float& y) {
    asm("mov.b64 {%0,%1}, %2;" : "=f"(x), "=f"(y) : "l"(v));
}
__device__ __forceinline__ ull fma2(ull a, ull b, ull c) {
    ull d; asm("fma.rn.f32x2 %0, %1, %2, %3;" : "=l"(d) : "l"(a), "l"(b), "l"(c)); return d;
}
__device__ __forceinline__ ull add2(ull a, ull b) {
    ull d; asm("add.rn.f32x2 %0, %1, %2;" : "=l"(d) : "l"(a), "l"(b)); return d;
}

__device__ __forceinline__ int loadBool(const void* p, int dt, long idx) {
    if (dt == 1) return ((const int*)p)[idx] != 0;
    if (dt == 0) return ((const unsigned char*)p)[idx] != 0;
    return ((const float*)p)[idx] != 0.f;
}

// ---------------------------------------------------------------------------
// Detect boolean storage dtype from the tags buffer (~30% true rate).
// ---------------------------------------------------------------------------
__global__ void detect_kernel(const unsigned int* __restrict__ w) {
    int i = threadIdx.x;
    int f = 0, u = 0;
#pragma unroll
    for (int q = 0; q < 4; q++) {
        unsigned int v = w[i + q * 256];
        if (v == 0x3F800000u) f = 1;
        else if (v & 0xFFFFFF00u) u = 1;
    }
    int anyf = __syncthreads_or(f);
    int anyu = __syncthreads_or(u);
    if (i == 0) g_bool_dt = anyf ? 2 : (anyu ? 0 : 1);
}

// ---------------------------------------------------------------------------
// Emissions GEMM + exp: eem[t][b][j] = exp(feats[t,b,:].W[:,j] + bias[j])
// CTA = 256 threads = 128 rows x 2 column-halves (12 ull acc each).
// ---------------------------------------------------------------------------
#define KT 32
__global__ __launch_bounds__(256) void emis_kernel(const float* __restrict__ feats,
                                                   const float* __restrict__ W,
                                                   const float* __restrict__ bias) {
    __shared__ float2 As[128 * 17];   // 128 rows x (16 f2 + pad) = 17 KB
    __shared__ float  Ws[KT * LLn];   // 32 x 48 = 6 KB
    const int tid = threadIdx.x;
    const int r = tid >> 1;           // row within CTA
    const int h = tid & 1;            // column half (0: j<24, 1: j>=24)
    const int base_row = blockIdx.x * 128;

    ull acc[12];
#pragma unroll
    for (int i = 0; i < 12; i++) acc[i] = 0ull;

    for (int kt = 0; kt < DD / KT; ++kt) {
        __syncthreads();
        {
            const float2* fg = (const float2*)(feats);
#pragma unroll
            for (int q = 0; q < 8; q++) {
                int n = q * 256 + tid;
                int rr = n >> 4;
                int c2 = n & 15;
                As[rr * 17 + c2] = fg[(size_t)(base_row + rr) * (DD / 2) + kt * (KT / 2) + c2];
            }
        }
        {
            const float4* wg = (const float4*)(W + kt * KT * LLn);
            float4* ws4 = (float4*)Ws;
            for (int n = tid; n < KT * LLn / 4; n += 256) ws4[n] = wg[n];
        }
        __syncthreads();

        const float2* arow = As + r * 17;
#pragma unroll
        for (int k2 = 0; k2 < 16; k2++) {
            float2 a2 = arow[k2];
            ull d0 = pack2(a2.x, a2.x);
            ull d1 = pack2(a2.y, a2.y);
            const ulonglong2* w0 = (const ulonglong2*)(Ws + (2 * k2) * LLn + h * 24);
            const ulonglong2* w1 = (const ulonglong2*)(Ws + (2 * k2 + 1) * LLn + h * 24);
#pragma unroll
            for (int j = 0; j < 6; j++) {
                ulonglong2 wa = w0[j];
                ulonglong2 wb = w1[j];
                acc[2 * j]     = fma2(d0, wa.x, acc[2 * j]);
                acc[2 * j + 1] = fma2(d0, wa.y, acc[2 * j + 1]);
                acc[2 * j]     = fma2(d1, wb.x, acc[2 * j]);
                acc[2 * j + 1] = fma2(d1, wb.y, acc[2 * j + 1]);
            }
        }
    }
    const int grow = base_row + r;       // = t*32 + b
    float* orow = g_eem + (size_t)grow * LLn + h * 24;
#pragma unroll
    for (int jp = 0; jp < 12; jp++) {
        float x, y; unpack2(acc[jp], x, y);
        float2 o;
        o.x = __expf(x + bias[h * 24 + 2 * jp]);
        o.y = __expf(y + bias[h * 24 + 2 * jp + 1]);
        ((float2*)orow)[jp] = o;
    }
}

// ---------------------------------------------------------------------------
// eemM = tags ? 0 : eem  (fully coalesced, float4/int4 vectorized)
// ---------------------------------------------------------------------------
__global__ __launch_bounds__(256) void mask_kernel(const void* __restrict__ tags) {
    int i = blockIdx.x * 256 + threadIdx.x;   // float4 index
    float4 e = ((const float4*)g_eem)[i];
    int dt = g_bool_dt;
    int b0, b1, b2, b3;
    if (dt == 1) {
        int4 t = ((const int4*)tags)[i];
        b0 = t.x != 0; b1 = t.y != 0; b2 = t.z != 0; b3 = t.w != 0;
    } else if (dt == 0) {
        uchar4 t = ((const uchar4*)tags)[i];
        b0 = t.x != 0; b1 = t.y != 0; b2 = t.z != 0; b3 = t.w != 0;
    } else {
        float4 t = ((const float4*)tags)[i];
        b0 = t.x != 0.f; b1 = t.y != 0.f; b2 = t.z != 0.f; b3 = t.w != 0.f;
    }
    if (b0) e.x = 0.f;
    if (b1) e.y = 0.f;
    if (b2) e.z = 0.f;
    if (b3) e.w = 0.f;
    ((float4*)g_eemM)[i] = e;
}

// ---------------------------------------------------------------------------
// CRF forward scan: ONE WARP per chain, smem u exchange, __syncwarp only.
// CTA per batch (64 threads): warp0 = fwd, warp1 = par — independent until a
// single final __syncthreads.
// Balanced work: lane l computes row l fully (24 fma2) + half the k-range of
// row 32+(l&15) (12 fma2, kp in [kh, kh+12)); halves combine via one
// shfl_xor(16)+add. Branch-free 8-step groups, renorm at static slot 7.
// ---------------------------------------------------------------------------
__global__ __launch_bounds__(64) void scan_kernel(float* __restrict__ out,
                                                  const int* __restrict__ lens,
                                                  const float* __restrict__ beg,
                                                  const float* __restrict__ trans,
                                                  const float* __restrict__ endv,
                                                  const void* __restrict__ bc,
                                                  const void* __restrict__ ec,
                                                  const void* __restrict__ tc) {
    __shared__ __align__(16) float ubuf[2][2][LLn];  // [warp][phase][row]
    __shared__ float res2[2];
    const int tid = threadIdx.x;
    const int w = tid >> 5;              // 0 = fwd, 1 = par
    const int l = tid & 31;
    const bool is_par = (w == 1);
    const int rA = l;                    // own row
    const int rB = 32 + (l & 15);        // shared row (two lanes, half-k each)
    const int kh = (l >> 4) * 12;        // this lane's kp offset into row B
    const bool storeB = l < 16;
    const int b = blockIdx.x;
    const int lenm1 = lens[b] - 1;
    const int dt = g_bool_dt;
    const float* gbA = (is_par ? g_eemM : g_eem) + b * LLn + rA;
    const float* gbB = (is_par ? g_eemM : g_eem) + b * LLn + rB;

    // Row A transitions: 24 packed (pairs over k). Row B: this lane's 12.
    ull EA[24], EB[12];
#pragma unroll
    for (int kp = 0; kp < 24; kp++) {
        float e0 = __expf(trans[rA * LLn + 2 * kp]);
        float e1 = __expf(trans[rA * LLn + 2 * kp + 1]);
        if (is_par) {
            if (loadBool(tc, dt, rA * LLn + 2 * kp))     e0 = 0.f;
            if (loadBool(tc, dt, rA * LLn + 2 * kp + 1)) e1 = 0.f;
        }
        EA[kp] = pack2(e0, e1);
    }
#pragma unroll
    for (int j = 0; j < 12; j++) {
        int kp = kh + j;
        float e0 = __expf(trans[rB * LLn + 2 * kp]);
        float e1 = __expf(trans[rB * LLn + 2 * kp + 1]);
        if (is_par) {
            if (loadBool(tc, dt, rB * LLn + 2 * kp))     e0 = 0.f;
            if (loadBool(tc, dt, rB * LLn + 2 * kp + 1)) e1 = 0.f;
        }
        EB[j] = pack2(e0, e1);
    }
    float EendA = __expf(endv[rA]);
    if (is_par && loadBool(ec, dt, rA)) EendA = 0.f;
    float EendB = 0.f;
    if (storeB) {                        // only lanes<16 contribute row B
        EendB = __expf(endv[rB]);
        if (is_par && loadBool(ec, dt, rB)) EendB = 0.f;
    }

    // t = 0 init (eemM folds tags; bc applied here)
    {
        float u0 = __ldg(gbA) * __expf(beg[rA]);
        if (is_par && loadBool(bc, dt, rA)) u0 = 0.f;
        ubuf[w][0][rA] = u0;
        if (storeB) {
            float u1 = __ldg(gbB) * __expf(beg[rB]);
            if (is_par && loadBool(bc, dt, rB)) u1 = 0.f;
            ubuf[w][0][rB] = u1;
        }
    }
    __syncwarp();

    float c = 0.f;
    int p = 0;
    int t = 1;
    float uAn = 0.f, uBn = 0.f;

    auto ldA = [&](int tt) -> float {
        int tq = (tt <= TT - 1) ? tt : (TT - 1);
        return __ldg(gbA + (size_t)tq * SSTRIDE);
    };
    auto ldB = [&](int tt) -> float {
        int tq = (tt <= TT - 1) ? tt : (TT - 1);
        return __ldg(gbB + (size_t)tq * SSTRIDE);
    };

    // One step: dots from smem u, combine B halves, scale by emissions.
    auto dots = [&](float peA, float peB) {
        const ull* u2 = (const ull*)(ubuf[w][p]);   // 24 packed u pairs
        ull aA0 = 0, aA1 = 0, aA2 = 0, aA3 = 0;
#pragma unroll
        for (int i = 0; i < 6; i++) {
            ull x0 = u2[4 * i];
            ull x1 = u2[4 * i + 1];
            ull x2 = u2[4 * i + 2];
            ull x3 = u2[4 * i + 3];
            aA0 = fma2(EA[4 * i],     x0, aA0);
            aA1 = fma2(EA[4 * i + 1], x1, aA1);
            aA2 = fma2(EA[4 * i + 2], x2, aA2);
            aA3 = fma2(EA[4 * i + 3], x3, aA3);
        }
        ull aB0 = 0, aB1 = 0;
        const ull* u2h = u2 + kh;        // pair index == kp  (kh, not 2*kh!)
#pragma unroll
        for (int i = 0; i < 6; i++) {
            aB0 = fma2(EB[2 * i],     u2h[2 * i],     aB0);
            aB1 = fma2(EB[2 * i + 1], u2h[2 * i + 1], aB1);
        }
        aA0 = add2(aA0, aA2); aA1 = add2(aA1, aA3); aA0 = add2(aA0, aA1);
        aB0 = add2(aB0, aB1);
        float xA, yA, xB, yB;
        unpack2(aA0, xA, yA); unpack2(aB0, xB, yB);
        float dA = xA + yA;
        float dBh = xB + yB;
        float dB = dBh + __shfl_xor_sync(0xffffffffu, dBh, 16);
        uAn = dA * peA;
        uBn = dB * peB;
    };

    auto commit = [&]() {
        ubuf[w][p ^ 1][rA] = uAn;
        if (storeB) ubuf[w][p ^ 1][rB] = uBn;
        p ^= 1;
        __syncwarp();
    };

    // rotating 8-slot emission prefetch (static indices -> stays in regs)
    float eA[8], eB[8];
#pragma unroll
    for (int i = 0; i < 8; i++) { eA[i] = ldA(1 + i); eB[i] = ldB(1 + i); }

    // ---- main loop: groups of 8 branch-free steps, renorm at slot 7 ----
    while (t + 8 <= lenm1) {
#pragma unroll
        for (int i = 0; i < 8; i++) {
            float pA = eA[i], pB = eB[i];
            eA[i] = ldA(t + 8 + i);
            eB[i] = ldB(t + 8 + i);
            dots(pA, pB);
            if (i == 7) {                // compile-time slot: branch-free
                float m = fmaxf(uAn, uBn);
#pragma unroll
                for (int off = 16; off >= 1; off >>= 1)
                    m = fmaxf(m, __shfl_xor_sync(0xffffffffu, m, off));
                m = fmaxf(m, 1e-30f);
                float inv = __fdividef(1.f, m);
                uAn *= inv; uBn *= inv;
                c += __logf(m);
            }
            commit();
        }
        t += 8;
    }

    // ---- tail: r plain steps (r in [0,7]), then the final step ----
    const int r = lenm1 - t;
    float fA = eA[0], fB = eB[0];
#pragma unroll
    for (int i = 0; i < 8; i++) if (i == r) { fA = eA[i]; fB = eB[i]; }

#pragma unroll
    for (int i = 0; i < 7; i++) {
        if (i < r) { dots(eA[i], eB[i]); commit(); }
    }

    // final step (t == lenm1): emission + end transition + logsumexp readout
    {
        dots(fA, fB);
        float s = uAn * EendA + uBn * EendB;  // EendB==0 on lanes >= 16
#pragma unroll
        for (int off = 16; off >= 1; off >>= 1)
            s += __shfl_xor_sync(0xffffffffu, s, off);
        if (l == 0) res2[w] = c + __logf(s);
    }

    __syncthreads();
    if (tid == 0) out[b] = res2[0] - res2[1];
}

extern "C" void kernel_launch(void* const* d_in, const int* in_sizes, int n_in,
                              void* d_out, int out_size) {
    const float* feats = (const float*)d_in[0];
    const void*  tags  = d_in[1];
    const int*   lens  = (const int*)d_in[2];
    const float* W     = (const float*)d_in[3];
    const float* bias  = (const float*)d_in[4];
    const float* beg   = (const float*)d_in[5];
    const float* trans = (const float*)d_in[6];
    const float* endv  = (const float*)d_in[7];
    const void*  bc    = d_in[8];
    const void*  ec    = d_in[9];
    const void*  tc    = d_in[10];

    emis_kernel<<<256, 256>>>(feats, W, bias);
    detect_kernel<<<1, 256>>>((const unsigned int*)tags);
    mask_kernel<<<TT * BB * LLn / 4 / 256, 256>>>(tags);
    scan_kernel<<<BB, 64>>>((float*)d_out, lens, beg, trans, endv, bc, ec, tc);
}

// round 13
// speedup vs baseline: 1.2772x; 1.1585x over previous
#include <cuda_runtime.h>

typedef unsigned long long ull;

#define TT 1024
#define BB 32
#define DD 768
#define LLn 48
#define SSTRIDE (BB * LLn)   // 1536 floats per time step

// Scratch (static device globals — no allocation)
__device__ float g_eem[TT * BB * LLn];   // exp(em + bias), layout [t][b][l]
__device__ float g_eemM[TT * BB * LLn];  // tags ? 0 : eem  (for partial chain)
__device__ float g_res[64];              // [0..31]=fwd, [32..63]=par
__device__ int   g_bool_dt;              // 0=uint8, 1=int32, 2=float32

__device__ __forceinline__ ull pack2(float x, float y) {
    ull r; asm("mov.b64 %0, {%1,%2};" : "=l"(r) : "f"(x), "f"(y)); return r;
}
__device__ __forceinline__ void unpack2(ull v, float& x, float& y) {
    asm("mov.b64 {%0,%1}, %2;" : "=f"(x), "=f"(y) : "l"(v));
}
__device__ __forceinline__ ull fma2(ull a, ull b, ull c) {
    ull d; asm("fma.rn.f32x2 %0, %1, %2, %3;" : "=l"(d) : "l"(a), "l"(b), "l"(c)); return d;
}
__device__ __forceinline__ ull add2(ull a, ull b) {
    ull d; asm("add.rn.f32x2 %0, %1, %2;" : "=l"(d) : "l"(a), "l"(b)); return d;
}

__device__ __forceinline__ int loadBool(const void* p, int dt, long idx) {
    if (dt == 1) return ((const int*)p)[idx] != 0;
    if (dt == 0) return ((const unsigned char*)p)[idx] != 0;
    return ((const float*)p)[idx] != 0.f;
}

// ---------------------------------------------------------------------------
// Detect boolean storage dtype from the tags buffer (~30% true rate).
// ---------------------------------------------------------------------------
__global__ void detect_kernel(const unsigned int* __restrict__ w) {
    int i = threadIdx.x;
    int f = 0, u = 0;
#pragma unroll
    for (int q = 0; q < 4; q++) {
        unsigned int v = w[i + q * 256];
        if (v == 0x3F800000u) f = 1;
        else if (v & 0xFFFFFF00u) u = 1;
    }
    int anyf = __syncthreads_or(f);
    int anyu = __syncthreads_or(u);
    if (i == 0) g_bool_dt = anyf ? 2 : (anyu ? 0 : 1);
}

// ---------------------------------------------------------------------------
// Emissions GEMM + exp: eem[t][b][j] = exp(feats[t,b,:].W[:,j] + bias[j])
// CTA = 256 threads = 128 rows x 2 column-halves (12 ull acc each).
// ---------------------------------------------------------------------------
#define KT 32
__global__ __launch_bounds__(256) void emis_kernel(const float* __restrict__ feats,
                                                   const float* __restrict__ W,
                                                   const float* __restrict__ bias) {
    __shared__ float2 As[128 * 17];   // 128 rows x (16 f2 + pad) = 17 KB
    __shared__ float  Ws[KT * LLn];   // 32 x 48 = 6 KB
    const int tid = threadIdx.x;
    const int r = tid >> 1;           // row within CTA
    const int h = tid & 1;            // column half (0: j<24, 1: j>=24)
    const int base_row = blockIdx.x * 128;

    ull acc[12];
#pragma unroll
    for (int i = 0; i < 12; i++) acc[i] = 0ull;

    for (int kt = 0; kt < DD / KT; ++kt) {
        __syncthreads();
        {
            const float2* fg = (const float2*)(feats);
#pragma unroll
            for (int q = 0; q < 8; q++) {
                int n = q * 256 + tid;
                int rr = n >> 4;
                int c2 = n & 15;
                As[rr * 17 + c2] = fg[(size_t)(base_row + rr) * (DD / 2) + kt * (KT / 2) + c2];
            }
        }
        {
            const float4* wg = (const float4*)(W + kt * KT * LLn);
            float4* ws4 = (float4*)Ws;
            for (int n = tid; n < KT * LLn / 4; n += 256) ws4[n] = wg[n];
        }
        __syncthreads();

        const float2* arow = As + r * 17;
#pragma unroll
        for (int k2 = 0; k2 < 16; k2++) {
            float2 a2 = arow[k2];
            ull d0 = pack2(a2.x, a2.x);
            ull d1 = pack2(a2.y, a2.y);
            const ulonglong2* w0 = (const ulonglong2*)(Ws + (2 * k2) * LLn + h * 24);
            const ulonglong2* w1 = (const ulonglong2*)(Ws + (2 * k2 + 1) * LLn + h * 24);
#pragma unroll
            for (int j = 0; j < 6; j++) {
                ulonglong2 wa = w0[j];
                ulonglong2 wb = w1[j];
                acc[2 * j]     = fma2(d0, wa.x, acc[2 * j]);
                acc[2 * j + 1] = fma2(d0, wa.y, acc[2 * j + 1]);
                acc[2 * j]     = fma2(d1, wb.x, acc[2 * j]);
                acc[2 * j + 1] = fma2(d1, wb.y, acc[2 * j + 1]);
            }
        }
    }
    const int grow = base_row + r;       // = t*32 + b
    float* orow = g_eem + (size_t)grow * LLn + h * 24;
#pragma unroll
    for (int jp = 0; jp < 12; jp++) {
        float x, y; unpack2(acc[jp], x, y);
        float2 o;
        o.x = __expf(x + bias[h * 24 + 2 * jp]);
        o.y = __expf(y + bias[h * 24 + 2 * jp + 1]);
        ((float2*)orow)[jp] = o;
    }
}

// ---------------------------------------------------------------------------
// eemM = tags ? 0 : eem  (fully coalesced, float4/int4 vectorized)
// ---------------------------------------------------------------------------
__global__ __launch_bounds__(256) void mask_kernel(const void* __restrict__ tags) {
    int i = blockIdx.x * 256 + threadIdx.x;   // float4 index
    float4 e = ((const float4*)g_eem)[i];
    int dt = g_bool_dt;
    int b0, b1, b2, b3;
    if (dt == 1) {
        int4 t = ((const int4*)tags)[i];
        b0 = t.x != 0; b1 = t.y != 0; b2 = t.z != 0; b3 = t.w != 0;
    } else if (dt == 0) {
        uchar4 t = ((const uchar4*)tags)[i];
        b0 = t.x != 0; b1 = t.y != 0; b2 = t.z != 0; b3 = t.w != 0;
    } else {
        float4 t = ((const float4*)tags)[i];
        b0 = t.x != 0.f; b1 = t.y != 0.f; b2 = t.z != 0.f; b3 = t.w != 0.f;
    }
    if (b0) e.x = 0.f;
    if (b1) e.y = 0.f;
    if (b2) e.z = 0.f;
    if (b3) e.w = 0.f;
    ((float4*)g_eemM)[i] = e;
}

// ---------------------------------------------------------------------------
// CRF forward scan: 3 warps per chain (96 threads), one chain per CTA.
// grid 64: bidx<32 fwd(b), else par(b). Lane g: row = g>>1, k-half = g&1.
// Every lane: 6 LDS.128 + 12 fma2; halves combine via shfl_xor(1) (adjacent
// lanes, same warp). One __syncthreads per step. Branch-free 8-step groups,
// renorm at static slot 7 (warp butterfly + 3 smem partials).
// ---------------------------------------------------------------------------
__global__ __launch_bounds__(96) void scan_kernel(const int* __restrict__ lens,
                                                  const float* __restrict__ beg,
                                                  const float* __restrict__ trans,
                                                  const float* __restrict__ endv,
                                                  const void* __restrict__ bc,
                                                  const void* __restrict__ ec,
                                                  const void* __restrict__ tc) {
    __shared__ __align__(16) float ubuf[2][LLn];
    __shared__ float wpart[3];
    const int g = threadIdx.x;           // 0..95
    const int warp = g >> 5;
    const int lane = g & 31;
    const int row = g >> 1;              // 0..47
    const int half = g & 1;              // k-half: [24*half, 24*half+24)
    const int bidx = blockIdx.x;
    const int b = bidx & 31;
    const bool is_par = bidx >= 32;
    const int lenm1 = lens[b] - 1;
    const int dt = g_bool_dt;
    const float* gb = (is_par ? g_eemM : g_eem) + b * LLn + row;

    // This lane's 12 packed transitions: row, k in [24*half, 24*half+24)
    ull EH[12];
#pragma unroll
    for (int j = 0; j < 12; j++) {
        int k = half * 24 + 2 * j;
        float e0 = __expf(trans[row * LLn + k]);
        float e1 = __expf(trans[row * LLn + k + 1]);
        if (is_par) {
            if (loadBool(tc, dt, row * LLn + k))     e0 = 0.f;
            if (loadBool(tc, dt, row * LLn + k + 1)) e1 = 0.f;
        }
        EH[j] = pack2(e0, e1);
    }
    float Eend = 0.f;
    if (half == 0) {                     // only half=0 contributes to final sum
        Eend = __expf(endv[row]);
        if (is_par && loadBool(ec, dt, row)) Eend = 0.f;
    }

    // t = 0 init (eemM folds tags; bc applied here)
    if (half == 0) {
        float u0 = __ldg(gb) * __expf(beg[row]);
        if (is_par && loadBool(bc, dt, row)) u0 = 0.f;
        ubuf[0][row] = u0;
    }
    __syncthreads();

    float c = 0.f;
    int p = 0;
    int t = 1;
    float val = 0.f;                     // this lane's row value (post-combine)

    auto ld = [&](int tt) -> float {
        int tq = (tt <= TT - 1) ? tt : (TT - 1);
        return __ldg(gb + (size_t)tq * SSTRIDE);
    };

    // One step: half-dot from smem u, combine adjacent-lane halves, scale.
    auto dots = [&](float pe) {
        const ull* u2 = (const ull*)(ubuf[p]) + half * 12;  // 12 pairs
        ull a0 = 0, a1 = 0, a2 = 0, a3 = 0;
#pragma unroll
        for (int i = 0; i < 3; i++) {
            ull x0 = u2[4 * i];
            ull x1 = u2[4 * i + 1];
            ull x2 = u2[4 * i + 2];
            ull x3 = u2[4 * i + 3];
            a0 = fma2(EH[4 * i],     x0, a0);
            a1 = fma2(EH[4 * i + 1], x1, a1);
            a2 = fma2(EH[4 * i + 2], x2, a2);
            a3 = fma2(EH[4 * i + 3], x3, a3);
        }
        a0 = add2(a0, a2); a1 = add2(a1, a3); a0 = add2(a0, a1);
        float x, y; unpack2(a0, x, y);
        float dh = x + y;
        float d = dh + __shfl_xor_sync(0xffffffffu, dh, 1);  // combine halves
        val = d * pe;
    };

    auto commit = [&]() {
        if (half == 0) ubuf[p ^ 1][row] = val;
        p ^= 1;
        __syncthreads();
    };

    // rotating 8-slot emission prefetch (static indices -> stays in regs)
    float e[8];
#pragma unroll
    for (int i = 0; i < 8; i++) e[i] = ld(1 + i);

    // ---- main loop: groups of 8 branch-free steps, renorm at slot 7 ----
    while (t + 8 <= lenm1) {
#pragma unroll
        for (int i = 0; i < 8; i++) {
            float pe = e[i];
            e[i] = ld(t + 8 + i);
            dots(pe);
            if (i == 7) {                // compile-time slot: branch-free
                float m = val;           // rows duplicated across lane pairs: harmless for max
#pragma unroll
                for (int off = 16; off >= 1; off >>= 1)
                    m = fmaxf(m, __shfl_xor_sync(0xffffffffu, m, off));
                if (lane == 0) wpart[warp] = m;
                __syncthreads();
                float mm = fmaxf(fmaxf(wpart[0], wpart[1]), fmaxf(wpart[2], 1e-30f));
                val *= __fdividef(1.f, mm);
                c += __logf(mm);
            }
            commit();
        }
        t += 8;
    }

    // ---- tail: r plain steps (r in [0,7]), then the final step ----
    const int r = lenm1 - t;
    float fe = e[0];
#pragma unroll
    for (int i = 0; i < 8; i++) if (i == r) fe = e[i];

#pragma unroll
    for (int i = 0; i < 7; i++) {
        if (i < r) { dots(e[i]); commit(); }
    }

    // final step (t == lenm1): emission + end transition + logsumexp readout
    {
        dots(fe);
        float s = val * Eend;            // Eend==0 on half=1 lanes: no double count
#pragma unroll
        for (int off = 16; off >= 1; off >>= 1)
            s += __shfl_xor_sync(0xffffffffu, s, off);
        if (lane == 0) wpart[warp] = s;
        __syncthreads();
        if (g == 0) g_res[bidx] = c + __logf(wpart[0] + wpart[1] + wpart[2]);
    }
}

__global__ void combine_kernel(float* __restrict__ out) {
    int i = threadIdx.x;
    if (i < BB) out[i] = g_res[i] - g_res[BB + i];
}

extern "C" void kernel_launch(void* const* d_in, const int* in_sizes, int n_in,
                              void* d_out, int out_size) {
    const float* feats = (const float*)d_in[0];
    const void*  tags  = d_in[1];
    const int*   lens  = (const int*)d_in[2];
    const float* W     = (const float*)d_in[3];
    const float* bias  = (const float*)d_in[4];
    const float* beg   = (const float*)d_in[5];
    const float* trans = (const float*)d_in[6];
    const float* endv  = (const float*)d_in[7];
    const void*  bc    = d_in[8];
    const void*  ec    = d_in[9];
    const void*  tc    = d_in[10];

    emis_kernel<<<256, 256>>>(feats, W, bias);
    detect_kernel<<<1, 256>>>((const unsigned int*)tags);
    mask_kernel<<<TT * BB * LLn / 4 / 256, 256>>>(tags);
    scan_kernel<<<64, 96>>>(lens, beg, trans, endv, bc, ec, tc);
    combine_kernel<<<1, 32>>>((float*)d_out);
}

// round 14
// speedup vs baseline: 1.3078x; 1.0240x over previous
#include <cuda_runtime.h>

typedef unsigned long long ull;

#define TT 1024
#define BB 32
#define DD 768
#define LLn 48
#define SSTRIDE (BB * LLn)   // 1536 floats per time step

// Scratch (static device globals — no allocation)
__device__ float g_eem[TT * BB * LLn];   // exp(em + bias), layout [t][b][l]
__device__ float g_eemM[TT * BB * LLn];  // tags ? 0 : eem  (for partial chain)
__device__ float g_res[64];              // [0..31]=fwd, [32..63]=par
__device__ int   g_bool_dt;              // 0=uint8, 1=int32, 2=float32

__device__ __forceinline__ ull pack2(float x, float y) {
    ull r; asm("mov.b64 %0, {%1,%2};" : "=l"(r) : "f"(x), "f"(y)); return r;
}
__device__ __forceinline__ void unpack2(ull v, float& x, float& y) {
    asm("mov.b64 {%0,%1}, %2;" : "=f"(x), "=f"(y) : "l"(v));
}
__device__ __forceinline__ ull fma2(ull a, ull b, ull c) {
    ull d; asm("fma.rn.f32x2 %0, %1, %2, %3;" : "=l"(d) : "l"(a), "l"(b), "l"(c)); return d;
}
__device__ __forceinline__ ull add2(ull a, ull b) {
    ull d; asm("add.rn.f32x2 %0, %1, %2;" : "=l"(d) : "l"(a), "l"(b)); return d;
}

__device__ __forceinline__ int loadBool(const void* p, int dt, long idx) {
    if (dt == 1) return ((const int*)p)[idx] != 0;
    if (dt == 0) return ((const unsigned char*)p)[idx] != 0;
    return ((const float*)p)[idx] != 0.f;
}

// ---------------------------------------------------------------------------
// Detect boolean storage dtype from the tags buffer (~30% true rate).
// ---------------------------------------------------------------------------
__global__ void detect_kernel(const unsigned int* __restrict__ w) {
    int i = threadIdx.x;
    int f = 0, u = 0;
#pragma unroll
    for (int q = 0; q < 4; q++) {
        unsigned int v = w[i + q * 256];
        if (v == 0x3F800000u) f = 1;
        else if (v & 0xFFFFFF00u) u = 1;
    }
    int anyf = __syncthreads_or(f);
    int anyu = __syncthreads_or(u);
    if (i == 0) g_bool_dt = anyf ? 2 : (anyu ? 0 : 1);
}

// ---------------------------------------------------------------------------
// Emissions GEMM + exp + tag-mask: writes both eem and eemM = tags ? 0 : eem.
// CTA = 256 threads = 128 rows x 2 column-halves (12 ull acc each).
// ---------------------------------------------------------------------------
#define KT 32
__global__ __launch_bounds__(256) void emis_kernel(const float* __restrict__ feats,
                                                   const float* __restrict__ W,
                                                   const float* __restrict__ bias,
                                                   const void* __restrict__ tags) {
    __shared__ float2 As[128 * 17];   // 128 rows x (16 f2 + pad) = 17 KB
    __shared__ float  Ws[KT * LLn];   // 32 x 48 = 6 KB
    const int tid = threadIdx.x;
    const int r = tid >> 1;           // row within CTA
    const int h = tid & 1;            // column half (0: j<24, 1: j>=24)
    const int base_row = blockIdx.x * 128;

    ull acc[12];
#pragma unroll
    for (int i = 0; i < 12; i++) acc[i] = 0ull;

    for (int kt = 0; kt < DD / KT; ++kt) {
        __syncthreads();
        {
            const float2* fg = (const float2*)(feats);
#pragma unroll
            for (int q = 0; q < 8; q++) {
                int n = q * 256 + tid;
                int rr = n >> 4;
                int c2 = n & 15;
                As[rr * 17 + c2] = fg[(size_t)(base_row + rr) * (DD / 2) + kt * (KT / 2) + c2];
            }
        }
        {
            const float4* wg = (const float4*)(W + kt * KT * LLn);
            float4* ws4 = (float4*)Ws;
            for (int n = tid; n < KT * LLn / 4; n += 256) ws4[n] = wg[n];
        }
        __syncthreads();

        const float2* arow = As + r * 17;
#pragma unroll
        for (int k2 = 0; k2 < 16; k2++) {
            float2 a2 = arow[k2];
            ull d0 = pack2(a2.x, a2.x);
            ull d1 = pack2(a2.y, a2.y);
            const ulonglong2* w0 = (const ulonglong2*)(Ws + (2 * k2) * LLn + h * 24);
            const ulonglong2* w1 = (const ulonglong2*)(Ws + (2 * k2 + 1) * LLn + h * 24);
#pragma unroll
            for (int j = 0; j < 6; j++) {
                ulonglong2 wa = w0[j];
                ulonglong2 wb = w1[j];
                acc[2 * j]     = fma2(d0, wa.x, acc[2 * j]);
                acc[2 * j + 1] = fma2(d0, wa.y, acc[2 * j + 1]);
                acc[2 * j]     = fma2(d1, wb.x, acc[2 * j]);
                acc[2 * j + 1] = fma2(d1, wb.y, acc[2 * j + 1]);
            }
        }
    }
    // Epilogue: bias + exp; write eem and tag-masked eemM.
    const int grow = base_row + r;       // = t*32 + b
    const long ebase = (long)grow * LLn + h * 24;
    const int dt = g_bool_dt;
    float* orow  = g_eem  + ebase;
    float* orowM = g_eemM + ebase;
#pragma unroll
    for (int jp = 0; jp < 12; jp++) {
        float x, y; unpack2(acc[jp], x, y);
        float2 o;
        o.x = __expf(x + bias[h * 24 + 2 * jp]);
        o.y = __expf(y + bias[h * 24 + 2 * jp + 1]);
        ((float2*)orow)[jp] = o;
        float2 om = o;
        if (loadBool(tags, dt, ebase + 2 * jp))     om.x = 0.f;
        if (loadBool(tags, dt, ebase + 2 * jp + 1)) om.y = 0.f;
        ((float2*)orowM)[jp] = om;
    }
}

// ---------------------------------------------------------------------------
// CRF forward scan: 3 warps per chain (96 threads), one chain per CTA.
// grid 64: bidx<32 fwd(b), else par(b). Lane g: row = g>>1, k-half = g&1.
// Every lane: 6 LDS.128 + 12 fma2; halves combine via shfl_xor(1).
// Fast main loop uses an incrementally-advanced pointer with static offsets
// (no clamping); clamped slow group + tail finish the sequence.
// ---------------------------------------------------------------------------
__global__ __launch_bounds__(96) void scan_kernel(const int* __restrict__ lens,
                                                  const float* __restrict__ beg,
                                                  const float* __restrict__ trans,
                                                  const float* __restrict__ endv,
                                                  const void* __restrict__ bc,
                                                  const void* __restrict__ ec,
                                                  const void* __restrict__ tc) {
    __shared__ __align__(16) float ubuf[2][LLn];
    __shared__ float wpart[3];
    const int g = threadIdx.x;           // 0..95
    const int warp = g >> 5;
    const int lane = g & 31;
    const int row = g >> 1;              // 0..47
    const int half = g & 1;              // k-half: [24*half, 24*half+24)
    const int bidx = blockIdx.x;
    const int b = bidx & 31;
    const bool is_par = bidx >= 32;
    const int lenm1 = lens[b] - 1;
    const int dt = g_bool_dt;
    const float* gb = (is_par ? g_eemM : g_eem) + b * LLn + row;

    // This lane's 12 packed transitions: row, k in [24*half, 24*half+24)
    ull EH[12];
#pragma unroll
    for (int j = 0; j < 12; j++) {
        int k = half * 24 + 2 * j;
        float e0 = __expf(trans[row * LLn + k]);
        float e1 = __expf(trans[row * LLn + k + 1]);
        if (is_par) {
            if (loadBool(tc, dt, row * LLn + k))     e0 = 0.f;
            if (loadBool(tc, dt, row * LLn + k + 1)) e1 = 0.f;
        }
        EH[j] = pack2(e0, e1);
    }
    float Eend = 0.f;
    if (half == 0) {                     // only half=0 contributes to final sum
        Eend = __expf(endv[row]);
        if (is_par && loadBool(ec, dt, row)) Eend = 0.f;
    }

    // t = 0 init (eemM folds tags; bc applied here)
    if (half == 0) {
        float u0 = __ldg(gb) * __expf(beg[row]);
        if (is_par && loadBool(bc, dt, row)) u0 = 0.f;
        ubuf[0][row] = u0;
    }
    __syncthreads();

    float c = 0.f;
    int p = 0;
    int t = 1;
    float val = 0.f;

    auto ld = [&](int tt) -> float {     // clamped (slow path / init only)
        int tq = (tt <= TT - 1) ? tt : (TT - 1);
        return __ldg(gb + (size_t)tq * SSTRIDE);
    };

    auto dots = [&](float pe) {
        const ull* u2 = (const ull*)(ubuf[p]) + half * 12;  // 12 pairs
        ull a0 = 0, a1 = 0, a2 = 0, a3 = 0;
#pragma unroll
        for (int i = 0; i < 3; i++) {
            ull x0 = u2[4 * i];
            ull x1 = u2[4 * i + 1];
            ull x2 = u2[4 * i + 2];
            ull x3 = u2[4 * i + 3];
            a0 = fma2(EH[4 * i],     x0, a0);
            a1 = fma2(EH[4 * i + 1], x1, a1);
            a2 = fma2(EH[4 * i + 2], x2, a2);
            a3 = fma2(EH[4 * i + 3], x3, a3);
        }
        a0 = add2(a0, a2); a1 = add2(a1, a3); a0 = add2(a0, a1);
        float x, y; unpack2(a0, x, y);
        float dh = x + y;
        float d = dh + __shfl_xor_sync(0xffffffffu, dh, 1);
        val = d * pe;
    };

    auto commit = [&]() {
        if (half == 0) ubuf[p ^ 1][row] = val;
        p ^= 1;
        __syncthreads();
    };

    auto renorm = [&]() {
        float m = val;
#pragma unroll
        for (int off = 16; off >= 1; off >>= 1)
            m = fmaxf(m, __shfl_xor_sync(0xffffffffu, m, off));
        if (lane == 0) wpart[warp] = m;
        __syncthreads();
        float mm = fmaxf(fmaxf(wpart[0], wpart[1]), fmaxf(wpart[2], 1e-30f));
        val *= __fdividef(1.f, mm);
        c += __logf(mm);
    };

    // 8-slot emission prefetch
    float e[8];
#pragma unroll
    for (int i = 0; i < 8; i++) e[i] = ld(1 + i);

    // ---- fast main loop: unclamped prefetch via advancing pointer ----
    const float* gp = gb + (size_t)9 * SSTRIDE;   // first prefetch target: t=9
    while (t + 16 <= lenm1) {                      // prefetch ids <= lenm1-1
        float en[8];
#pragma unroll
        for (int i = 0; i < 8; i++) en[i] = __ldg(gp + (size_t)i * SSTRIDE);
        gp += (size_t)8 * SSTRIDE;
#pragma unroll
        for (int i = 0; i < 8; i++) {
            dots(e[i]);
            if (i == 7) renorm();
            commit();
        }
#pragma unroll
        for (int i = 0; i < 8; i++) e[i] = en[i];
        t += 8;
    }

    // ---- slow group: clamped prefetch (at most one group of 8) ----
    while (t + 8 <= lenm1) {
#pragma unroll
        for (int i = 0; i < 8; i++) {
            float pe = e[i];
            e[i] = ld(t + 8 + i);
            dots(pe);
            if (i == 7) renorm();
            commit();
        }
        t += 8;
    }

    // ---- tail: r plain steps (r in [0,7]), then the final step ----
    const int r = lenm1 - t;
    float fe = e[0];
#pragma unroll
    for (int i = 0; i < 8; i++) if (i == r) fe = e[i];

#pragma unroll
    for (int i = 0; i < 7; i++) {
        if (i < r) { dots(e[i]); commit(); }
    }

    // final step (t == lenm1): emission + end transition + logsumexp readout
    {
        dots(fe);
        float s = val * Eend;            // Eend==0 on half=1 lanes
#pragma unroll
        for (int off = 16; off >= 1; off >>= 1)
            s += __shfl_xor_sync(0xffffffffu, s, off);
        if (lane == 0) wpart[warp] = s;
        __syncthreads();
        if (g == 0) g_res[bidx] = c + __logf(wpart[0] + wpart[1] + wpart[2]);
    }
}

__global__ void combine_kernel(float* __restrict__ out) {
    int i = threadIdx.x;
    if (i < BB) out[i] = g_res[i] - g_res[BB + i];
}

extern "C" void kernel_launch(void* const* d_in, const int* in_sizes, int n_in,
                              void* d_out, int out_size) {
    const float* feats = (const float*)d_in[0];
    const void*  tags  = d_in[1];
    const int*   lens  = (const int*)d_in[2];
    const float* W     = (const float*)d_in[3];
    const float* bias  = (const float*)d_in[4];
    const float* beg   = (const float*)d_in[5];
    const float* trans = (const float*)d_in[6];
    const float* endv  = (const float*)d_in[7];
    const void*  bc    = d_in[8];
    const void*  ec    = d_in[9];
    const void*  tc    = d_in[10];

    detect_kernel<<<1, 256>>>((const unsigned int*)tags);
    emis_kernel<<<256, 256>>>(feats, W, bias, tags);
    scan_kernel<<<64, 96>>>(lens, beg, trans, endv, bc, ec, tc);
    combine_kernel<<<1, 32>>>((float*)d_out);
}